// round 6
// baseline (speedup 1.0000x reference)
#include <cuda_runtime.h>
#include <cuda_bf16.h>
#include <cstdint>

// ---------------- problem dims ----------------
#define B_DIM 4096
#define SF    256
#define FC    512
#define ADIM  16
#define NSLOT 17            // 16 advantage slots + 1 state slot

// ---------------- GEMM tiles ------------------
#define BM 128
#define BN 256
#define BK 32
#define NT 256              // 8 warps: 2 (M) x 4 (N), warp tile 64x64

#define SROW   40                       // smem row stride in halves = 80 bytes
#define APLANE (128 * SROW * 2)         // 10240 B
#define BPLANE (256 * SROW * 2)         // 20480 B
#define SM_AHI 0
#define SM_ALO APLANE
#define SM_BHI (2 * APLANE)
#define SM_BLO (2 * APLANE + BPLANE)
#define STAGE_BYTES (2 * APLANE + 2 * BPLANE)   // 61440
#define STAGES 2
#define SM_BIAS (STAGES * STAGE_BYTES)          // 122880
#define SMEM_TOTAL (SM_BIAS + BN * 4)           // 123904

// ---------------- device scratch (no cudaMalloc allowed) ----
__device__ __nv_bfloat16 g_xhi[(size_t)B_DIM * SF];
__device__ __nv_bfloat16 g_xlo[(size_t)B_DIM * SF];
__device__ __nv_bfloat16 g_H1hi[(size_t)NSLOT * B_DIM * FC];
__device__ __nv_bfloat16 g_H1lo[(size_t)NSLOT * B_DIM * FC];
__device__ __nv_bfloat16 g_H2hi[(size_t)NSLOT * B_DIM * FC];
__device__ __nv_bfloat16 g_H2lo[(size_t)NSLOT * B_DIM * FC];
__device__ __nv_bfloat16 g_W1hi[(size_t)NSLOT * FC * SF];
__device__ __nv_bfloat16 g_W1lo[(size_t)NSLOT * FC * SF];
__device__ __nv_bfloat16 g_W2hi[(size_t)NSLOT * FC * FC];
__device__ __nv_bfloat16 g_W2lo[(size_t)NSLOT * FC * FC];
__device__ __nv_bfloat16 g_W3hi[(size_t)NSLOT * SF * FC];
__device__ __nv_bfloat16 g_W3lo[(size_t)NSLOT * SF * FC];
__device__ float g_S[(size_t)B_DIM * SF];

// ---------------- helpers ----------------
__device__ __forceinline__ uint32_t smem_u32(const void* p) {
    uint32_t a;
    asm("{ .reg .u64 t; cvta.to.shared.u64 t, %1; cvt.u32.u64 %0, t; }" : "=r"(a) : "l"(p));
    return a;
}
__device__ __forceinline__ void ldm_x4(uint32_t* r, uint32_t addr) {
    asm volatile("ldmatrix.sync.aligned.m8n8.x4.shared.b16 {%0,%1,%2,%3}, [%4];"
                 : "=r"(r[0]), "=r"(r[1]), "=r"(r[2]), "=r"(r[3]) : "r"(addr));
}
__device__ __forceinline__ void mma16816(float* d, const uint32_t* a, const uint32_t* b) {
    asm volatile("mma.sync.aligned.m16n8k16.row.col.f32.bf16.bf16.f32 "
                 "{%0,%1,%2,%3}, {%4,%5,%6,%7}, {%8,%9}, {%0,%1,%2,%3};"
                 : "+f"(d[0]), "+f"(d[1]), "+f"(d[2]), "+f"(d[3])
                 : "r"(a[0]), "r"(a[1]), "r"(a[2]), "r"(a[3]), "r"(b[0]), "r"(b[1]));
}
__device__ __forceinline__ void cpasync16(uint32_t dst, const void* src) {
    asm volatile("cp.async.cg.shared.global [%0], [%1], 16;" :: "r"(dst), "l"(src));
}
#define CP_COMMIT() asm volatile("cp.async.commit_group;" ::: "memory")
#define CP_WAIT1()  asm volatile("cp.async.wait_group 1;" ::: "memory")

// ======================================================================
// Prologue 1: elementwise split fp32 -> bf16 hi/lo
// ======================================================================
__global__ void split_kernel(const float* __restrict__ src,
                             __nv_bfloat16* __restrict__ dhi,
                             __nv_bfloat16* __restrict__ dlo, int n4) {
    int i = blockIdx.x * blockDim.x + threadIdx.x;
    if (i >= n4) return;
    float4 v = reinterpret_cast<const float4*>(src)[i];
    __nv_bfloat162 h0, h1, l0, l1;
    h0.x = __float2bfloat16(v.x); l0.x = __float2bfloat16(v.x - __bfloat162float(h0.x));
    h0.y = __float2bfloat16(v.y); l0.y = __float2bfloat16(v.y - __bfloat162float(h0.y));
    h1.x = __float2bfloat16(v.z); l1.x = __float2bfloat16(v.z - __bfloat162float(h1.x));
    h1.y = __float2bfloat16(v.w); l1.y = __float2bfloat16(v.w - __bfloat162float(h1.y));
    reinterpret_cast<__nv_bfloat162*>(dhi)[2 * i] = h0;
    reinterpret_cast<__nv_bfloat162*>(dhi)[2 * i + 1] = h1;
    reinterpret_cast<__nv_bfloat162*>(dlo)[2 * i] = l0;
    reinterpret_cast<__nv_bfloat162*>(dlo)[2 * i + 1] = l1;
}

// ======================================================================
// Prologue 2: transpose [K,N] fp32 -> [N,K] bf16 hi/lo; slot 16 = alt src
// ======================================================================
__global__ void transpose_split(const float* __restrict__ src_main, size_t sstride,
                                const float* __restrict__ src_alt,
                                __nv_bfloat16* __restrict__ dhi,
                                __nv_bfloat16* __restrict__ dlo, int K, int N) {
    __shared__ float tile[32][33];
    const int a = blockIdx.z;
    const float* src = (a < ADIM) ? (src_main + (size_t)a * sstride) : src_alt;
    const int k0 = blockIdx.x * 32, n0 = blockIdx.y * 32;
    const int tx = threadIdx.x, ty = threadIdx.y;   // 32 x 8
#pragma unroll
    for (int r = 0; r < 32; r += 8)
        tile[ty + r][tx] = src[(size_t)(k0 + ty + r) * N + n0 + tx];
    __syncthreads();
    const size_t obase = ((size_t)a * N + n0) * K + k0;
#pragma unroll
    for (int r = 0; r < 32; r += 8) {
        float v = tile[tx][ty + r];
        __nv_bfloat16 h = __float2bfloat16(v);
        dhi[obase + (size_t)(ty + r) * K + tx] = h;
        dlo[obase + (size_t)(ty + r) * K + tx] = __float2bfloat16(v - __bfloat162float(h));
    }
}

// ======================================================================
// Batched GEMM: O = [relu](A @ W^T + bias), pre-split bf16 operands.
// warp tile 64x64, CTA tile 128x256, 2-stage cp.async pipeline.
// outmode 0: write bf16 hi/lo planes. outmode 1: fp32 (main/alt).
// ======================================================================
__global__ void __launch_bounds__(NT, 1)
gemm_mma(const __nv_bfloat16* __restrict__ Ahi, const __nv_bfloat16* __restrict__ Alo,
         size_t sAz,
         const __nv_bfloat16* __restrict__ Whi, const __nv_bfloat16* __restrict__ Wlo,
         size_t sWz,
         const float* __restrict__ bmain, size_t sbz, const float* __restrict__ balt,
         __nv_bfloat16* __restrict__ Ohi, __nv_bfloat16* __restrict__ Olo, size_t sOz,
         float* __restrict__ Ofm, size_t sOfz, int ldo_f,
         float* __restrict__ Ofa, int ldo_a,
         int K, int ldn, int relu_f, int outmode)
{
    extern __shared__ __align__(16) char smem[];
    const uint32_t smem_base = smem_u32(smem);
    const int tid  = threadIdx.x;
    const int wid  = tid >> 5;
    const int lane = tid & 31;
    const int wm   = wid >> 2;           // 0..1 (64 rows each)
    const int wn   = wid & 3;            // 0..3 (64 cols each)
    const int a   = blockIdx.z;
    const int m0  = blockIdx.x * BM;
    const int n0  = blockIdx.y * BN;

    const __nv_bfloat16* Ahs = Ahi + (size_t)a * sAz;
    const __nv_bfloat16* Als = Alo + (size_t)a * sAz;
    const __nv_bfloat16* Whs = Whi + (size_t)a * sWz;
    const __nv_bfloat16* Wls = Wlo + (size_t)a * sWz;
    const float* bsel = (a < ADIM) ? (bmain + (size_t)a * sbz) : balt;

    float* sBias = (float*)(smem + SM_BIAS);
    sBias[tid] = bsel[n0 + tid];         // NT == BN

    const size_t Ksz = (size_t)K;

    // cp.async task geometry:
    // A: 512 16B-chunks per plane -> 2/thread; B: 1024 per plane -> 4/thread.
    auto prefetch = [&](int stage, int c) {
        const uint32_t sb = smem_base + stage * STAGE_BYTES;
        const size_t kA = (size_t)c * BK;
#pragma unroll
        for (int r = 0; r < 2; ++r) {
            int t = tid * 2 + r;
            int row = t >> 2, ch = t & 3;
            size_t off = (size_t)(m0 + row) * Ksz + kA + ch * 8;
            uint32_t d = sb + SM_AHI + row * 80 + ch * 16;
            cpasync16(d, Ahs + off);
            cpasync16(d + (SM_ALO - SM_AHI), Als + off);
        }
#pragma unroll
        for (int r = 0; r < 4; ++r) {
            int t = tid * 4 + r;
            int row = t >> 2, ch = t & 3;
            size_t off = (size_t)(n0 + row) * Ksz + kA + ch * 8;
            uint32_t d = sb + SM_BHI + row * 80 + ch * 16;
            cpasync16(d, Whs + off);
            cpasync16(d + (SM_BLO - SM_BHI), Wls + off);
        }
    };

    float acc[4][8][4];
#pragma unroll
    for (int i = 0; i < 4; ++i)
#pragma unroll
        for (int j = 0; j < 8; ++j)
#pragma unroll
            for (int q = 0; q < 4; ++q) acc[i][j][q] = 0.f;

    // fragment addressing
    const int arow  = wm * 64 + (lane & 15);
    const int acol8 = (lane >> 4) * 8;
    // B x4: lanes 0-7: n+0..7 k0-7 | 8-15: n+0..7 k8-15 | 16-23: n+8.. k0-7 | 24-31: n+8.. k8-15
    const int brow_l = (lane >> 4) * 8 + (lane & 7);     // + wn*64 + p*16
    const int bk_l   = ((lane >> 3) & 1) * 8;            // + ks*16

    const int nch = K / BK;
    prefetch(0, 0); CP_COMMIT();

    for (int c = 0; c < nch; ++c) {
        if (c + 1 < nch) prefetch((c + 1) & 1, c + 1);
        CP_COMMIT();
        CP_WAIT1();
        __syncthreads();

        const uint32_t sb = smem_base + (c & 1) * STAGE_BYTES;
        const uint32_t aHiB = sb + SM_AHI, aLoB = sb + SM_ALO;
        const uint32_t bHiB = sb + SM_BHI, bLoB = sb + SM_BLO;

#pragma unroll
        for (int ks = 0; ks < 2; ++ks) {
            uint32_t ah[4][4], al[4][4], bh[8][2], bl[8][2];
#pragma unroll
            for (int i = 0; i < 4; ++i) {
                uint32_t off = (uint32_t)((arow + i * 16) * SROW + ks * 16 + acol8) * 2;
                ldm_x4(ah[i], aHiB + off);
                ldm_x4(al[i], aLoB + off);
            }
#pragma unroll
            for (int p = 0; p < 4; ++p) {
                uint32_t off = (uint32_t)((wn * 64 + p * 16 + brow_l) * SROW + ks * 16 + bk_l) * 2;
                ldm_x4(&bh[2 * p][0], bHiB + off);
                ldm_x4(&bl[2 * p][0], bLoB + off);
            }
#pragma unroll
            for (int i = 0; i < 4; ++i)
#pragma unroll
                for (int j = 0; j < 8; ++j) {
                    mma16816(acc[i][j], ah[i], bh[j]);
                    mma16816(acc[i][j], ah[i], bl[j]);
                    mma16816(acc[i][j], al[i], bh[j]);
                }
        }
        __syncthreads();
    }

    // ---- epilogue ----
    const int erow0 = wm * 64 + (lane >> 2);
    const int ecol0 = wn * 64 + 2 * (lane & 3);

    if (outmode == 0) {
        __nv_bfloat16* OhS = Ohi + (size_t)a * sOz;
        __nv_bfloat16* OlS = Olo + (size_t)a * sOz;
#pragma unroll
        for (int i = 0; i < 4; ++i) {
#pragma unroll
            for (int j = 0; j < 8; ++j) {
                int n_loc = ecol0 + j * 8;
                float bx = sBias[n_loc], by = sBias[n_loc + 1];
                float vx0 = acc[i][j][0] + bx, vy0 = acc[i][j][1] + by;
                float vx1 = acc[i][j][2] + bx, vy1 = acc[i][j][3] + by;
                if (relu_f) {
                    vx0 = fmaxf(vx0, 0.f); vy0 = fmaxf(vy0, 0.f);
                    vx1 = fmaxf(vx1, 0.f); vy1 = fmaxf(vy1, 0.f);
                }
                __nv_bfloat162 h0, l0, h1, l1;
                h0.x = __float2bfloat16(vx0); l0.x = __float2bfloat16(vx0 - __bfloat162float(h0.x));
                h0.y = __float2bfloat16(vy0); l0.y = __float2bfloat16(vy0 - __bfloat162float(h0.y));
                h1.x = __float2bfloat16(vx1); l1.x = __float2bfloat16(vx1 - __bfloat162float(h1.x));
                h1.y = __float2bfloat16(vy1); l1.y = __float2bfloat16(vy1 - __bfloat162float(h1.y));
                size_t p0 = (size_t)(m0 + erow0 + i * 16) * (size_t)ldn + n0 + n_loc;
                size_t p1 = (size_t)(m0 + erow0 + i * 16 + 8) * (size_t)ldn + n0 + n_loc;
                *reinterpret_cast<__nv_bfloat162*>(OhS + p0) = h0;
                *reinterpret_cast<__nv_bfloat162*>(OlS + p0) = l0;
                *reinterpret_cast<__nv_bfloat162*>(OhS + p1) = h1;
                *reinterpret_cast<__nv_bfloat162*>(OlS + p1) = l1;
            }
        }
    } else {
        float* Op;
        int ldo;
        if (a < ADIM) { Op = Ofm + (size_t)a * sOfz; ldo = ldo_f; }
        else          { Op = Ofa;                    ldo = ldo_a; }
#pragma unroll
        for (int i = 0; i < 4; ++i) {
#pragma unroll
            for (int j = 0; j < 8; ++j) {
                int n_loc = ecol0 + j * 8;
                float bx = sBias[n_loc], by = sBias[n_loc + 1];
                float2 v0, v1;
                v0.x = acc[i][j][0] + bx; v0.y = acc[i][j][1] + by;
                v1.x = acc[i][j][2] + bx; v1.y = acc[i][j][3] + by;
                if (relu_f) {
                    v0.x = fmaxf(v0.x, 0.f); v0.y = fmaxf(v0.y, 0.f);
                    v1.x = fmaxf(v1.x, 0.f); v1.y = fmaxf(v1.y, 0.f);
                }
                float* p0 = Op + (size_t)(m0 + erow0 + i * 16) * (size_t)ldo + n0 + n_loc;
                float* p1 = Op + (size_t)(m0 + erow0 + i * 16 + 8) * (size_t)ldo + n0 + n_loc;
                *reinterpret_cast<float2*>(p0) = v0;
                *reinterpret_cast<float2*>(p1) = v1;
            }
        }
    }
}

// ======================================================================
// Combine: psi[b,a,s] = state[b,s] + adv[b,a,s] - mean_a(adv[b,a,s])
// ======================================================================
__global__ void combine_kernel(float* __restrict__ out, const float* __restrict__ state) {
    int idx = blockIdx.x * blockDim.x + threadIdx.x;
    int b = idx >> 6;
    int s4 = (idx & 63) << 2;
    float4* base = reinterpret_cast<float4*>(out + (size_t)b * (ADIM * SF) + s4);
    float4 adv[ADIM];
    float sx = 0.f, sy = 0.f, sz = 0.f, sw = 0.f;
#pragma unroll
    for (int a2 = 0; a2 < ADIM; ++a2) {
        adv[a2] = base[a2 * (SF / 4)];
        sx += adv[a2].x; sy += adv[a2].y; sz += adv[a2].z; sw += adv[a2].w;
    }
    const float inv = 1.0f / ADIM;
    float4 st = *reinterpret_cast<const float4*>(state + (size_t)b * SF + s4);
    float mx = st.x - sx * inv, my = st.y - sy * inv;
    float mz = st.z - sz * inv, mw = st.w - sw * inv;
#pragma unroll
    for (int a2 = 0; a2 < ADIM; ++a2) {
        float4 v;
        v.x = adv[a2].x + mx; v.y = adv[a2].y + my;
        v.z = adv[a2].z + mz; v.w = adv[a2].w + mw;
        base[a2 * (SF / 4)] = v;
    }
}

// ======================================================================
extern "C" void kernel_launch(void* const* d_in, const int* in_sizes, int n_in,
                              void* d_out, int out_size) {
    const float* x  = (const float*)d_in[0];
    const float* W1 = (const float*)d_in[1];
    const float* b1 = (const float*)d_in[2];
    const float* W2 = (const float*)d_in[3];
    const float* b2 = (const float*)d_in[4];
    const float* W3 = (const float*)d_in[5];
    const float* b3 = (const float*)d_in[6];
    const float* V1 = (const float*)d_in[7];
    const float* c1 = (const float*)d_in[8];
    const float* V2 = (const float*)d_in[9];
    const float* c2 = (const float*)d_in[10];
    const float* V3 = (const float*)d_in[11];
    const float* c3 = (const float*)d_in[12];
    float* out = (float*)d_out;

    __nv_bfloat16 *xhi, *xlo, *H1hi, *H1lo, *H2hi, *H2lo;
    __nv_bfloat16 *W1hi, *W1lo, *W2hi, *W2lo, *W3hi, *W3lo;
    float* S;
    cudaGetSymbolAddress((void**)&xhi,  g_xhi);
    cudaGetSymbolAddress((void**)&xlo,  g_xlo);
    cudaGetSymbolAddress((void**)&H1hi, g_H1hi);
    cudaGetSymbolAddress((void**)&H1lo, g_H1lo);
    cudaGetSymbolAddress((void**)&H2hi, g_H2hi);
    cudaGetSymbolAddress((void**)&H2lo, g_H2lo);
    cudaGetSymbolAddress((void**)&W1hi, g_W1hi);
    cudaGetSymbolAddress((void**)&W1lo, g_W1lo);
    cudaGetSymbolAddress((void**)&W2hi, g_W2hi);
    cudaGetSymbolAddress((void**)&W2lo, g_W2lo);
    cudaGetSymbolAddress((void**)&W3hi, g_W3hi);
    cudaGetSymbolAddress((void**)&W3lo, g_W3lo);
    cudaGetSymbolAddress((void**)&S,    g_S);

    cudaFuncSetAttribute(gemm_mma, cudaFuncAttributeMaxDynamicSharedMemorySize, SMEM_TOTAL);

    // ---- prologue: split x; transpose+split weights (slot 16 = V branch) ----
    split_kernel<<<(B_DIM * SF / 4 + 255) / 256, 256>>>(x, xhi, xlo, B_DIM * SF / 4);
    transpose_split<<<dim3(SF / 32, FC / 32, NSLOT), dim3(32, 8)>>>(
        W1, (size_t)SF * FC, V1, W1hi, W1lo, SF, FC);
    transpose_split<<<dim3(FC / 32, FC / 32, NSLOT), dim3(32, 8)>>>(
        W2, (size_t)FC * FC, V2, W2hi, W2lo, FC, FC);
    transpose_split<<<dim3(FC / 32, SF / 32, NSLOT), dim3(32, 8)>>>(
        W3, (size_t)FC * SF, V3, W3hi, W3lo, FC, SF);

    const size_t sH = (size_t)B_DIM * FC;

    // Layer 1: x[B,256] @ W1^T -> H1 planes (A stride 0: all slots read x)
    gemm_mma<<<dim3(B_DIM / BM, FC / BN, NSLOT), NT, SMEM_TOTAL>>>(
        xhi, xlo, 0,
        W1hi, W1lo, (size_t)FC * SF,
        b1, FC, c1,
        H1hi, H1lo, sH,
        nullptr, 0, 0, nullptr, 0,
        SF, FC, 1, 0);

    // Layer 2: H1 @ W2^T -> H2 planes
    gemm_mma<<<dim3(B_DIM / BM, FC / BN, NSLOT), NT, SMEM_TOTAL>>>(
        H1hi, H1lo, sH,
        W2hi, W2lo, (size_t)FC * FC,
        b2, FC, c2,
        H2hi, H2lo, sH,
        nullptr, 0, 0, nullptr, 0,
        FC, FC, 1, 0);

    // Layer 3: H2 @ W3^T -> adv (fp32, into out) ; slot 16 -> g_S
    gemm_mma<<<dim3(B_DIM / BM, SF / BN, NSLOT), NT, SMEM_TOTAL>>>(
        H2hi, H2lo, sH,
        W3hi, W3lo, (size_t)SF * FC,
        b3, SF, c3,
        nullptr, nullptr, 0,
        out, SF, ADIM * SF,
        S, SF,
        FC, SF, 0, 1);

    // Combine
    combine_kernel<<<(B_DIM * SF / 4) / 256, 256>>>(out, S);
}

// round 8
// speedup vs baseline: 1.5237x; 1.5237x over previous
#include <cuda_runtime.h>
#include <cuda_fp16.h>
#include <cstdint>

// ---------------- problem dims ----------------
#define B_DIM 4096
#define SF    256
#define FC    512
#define ADIM  16
#define NSLOT 17            // 16 advantage slots + 1 state slot

// ---------------- GEMM tiles ------------------
#define BM 128
#define BN 128
#define BK 32
#define NT 256              // 8 warps: 2 (M) x 4 (N), warp tile 64x32

#define SROW   40                        // smem row stride in halves = 80 bytes
#define PLANE  (128 * SROW * 2)          // 10240 B per plane (128 rows)
#define SM_A   0
#define SM_BHI PLANE
#define SM_BLO (2 * PLANE)
#define STAGE_BYTES (3 * PLANE)          // 30720
#define STAGES 4
#define SM_BIAS (STAGES * STAGE_BYTES)   // 122880
#define SMEM_TOTAL (SM_BIAS + BN * 4)    // 123392

// ---------------- device scratch (no cudaMalloc allowed) ----
__device__ __half g_x[(size_t)B_DIM * SF];                    // fp16 activations
__device__ __half g_H1[(size_t)NSLOT * B_DIM * FC];
__device__ __half g_H2[(size_t)NSLOT * B_DIM * FC];
// transposed + exactly-split weights: [slot][N][K], W = hi + lo
__device__ __half g_W1hi[(size_t)NSLOT * FC * SF];
__device__ __half g_W1lo[(size_t)NSLOT * FC * SF];
__device__ __half g_W2hi[(size_t)NSLOT * FC * FC];
__device__ __half g_W2lo[(size_t)NSLOT * FC * FC];
__device__ __half g_W3hi[(size_t)NSLOT * SF * FC];
__device__ __half g_W3lo[(size_t)NSLOT * SF * FC];
__device__ float g_S[(size_t)B_DIM * SF];

// ---------------- helpers ----------------
__device__ __forceinline__ uint32_t smem_u32(const void* p) {
    uint32_t a;
    asm("{ .reg .u64 t; cvta.to.shared.u64 t, %1; cvt.u32.u64 %0, t; }" : "=r"(a) : "l"(p));
    return a;
}
__device__ __forceinline__ void ldm_x4(uint32_t* r, uint32_t addr) {
    asm volatile("ldmatrix.sync.aligned.m8n8.x4.shared.b16 {%0,%1,%2,%3}, [%4];"
                 : "=r"(r[0]), "=r"(r[1]), "=r"(r[2]), "=r"(r[3]) : "r"(addr));
}
__device__ __forceinline__ void ldm_x2(uint32_t* r, uint32_t addr) {
    asm volatile("ldmatrix.sync.aligned.m8n8.x2.shared.b16 {%0,%1}, [%2];"
                 : "=r"(r[0]), "=r"(r[1]) : "r"(addr));
}
__device__ __forceinline__ void mma16816(float* d, const uint32_t* a, const uint32_t* b) {
    asm volatile("mma.sync.aligned.m16n8k16.row.col.f32.f16.f16.f32 "
                 "{%0,%1,%2,%3}, {%4,%5,%6,%7}, {%8,%9}, {%0,%1,%2,%3};"
                 : "+f"(d[0]), "+f"(d[1]), "+f"(d[2]), "+f"(d[3])
                 : "r"(a[0]), "r"(a[1]), "r"(a[2]), "r"(a[3]), "r"(b[0]), "r"(b[1]));
}
__device__ __forceinline__ void cpasync16(uint32_t dst, const void* src) {
    asm volatile("cp.async.cg.shared.global [%0], [%1], 16;" :: "r"(dst), "l"(src));
}
#define CP_COMMIT() asm volatile("cp.async.commit_group;" ::: "memory")
#define CP_WAIT2()  asm volatile("cp.async.wait_group 2;" ::: "memory")

// ======================================================================
// Prologue 1: round fp32 -> fp16 (activations input)
// ======================================================================
__global__ void round_kernel(const float* __restrict__ src,
                             __half* __restrict__ dst, int n4) {
    int i = blockIdx.x * blockDim.x + threadIdx.x;
    if (i >= n4) return;
    float4 v = reinterpret_cast<const float4*>(src)[i];
    __half2 h0 = __floats2half2_rn(v.x, v.y);
    __half2 h1 = __floats2half2_rn(v.z, v.w);
    reinterpret_cast<__half2*>(dst)[2 * i] = h0;
    reinterpret_cast<__half2*>(dst)[2 * i + 1] = h1;
}

// ======================================================================
// Prologue 2: transpose [K,N] fp32 -> [N,K] fp16 hi/lo; slot 16 = alt src
// W = hi + lo exactly to ~21 bits.
// ======================================================================
__global__ void transpose_split(const float* __restrict__ src_main, size_t sstride,
                                const float* __restrict__ src_alt,
                                __half* __restrict__ dhi,
                                __half* __restrict__ dlo, int K, int N) {
    __shared__ float tile[32][33];
    const int a = blockIdx.z;
    const float* src = (a < ADIM) ? (src_main + (size_t)a * sstride) : src_alt;
    const int k0 = blockIdx.x * 32, n0 = blockIdx.y * 32;
    const int tx = threadIdx.x, ty = threadIdx.y;   // 32 x 8
#pragma unroll
    for (int r = 0; r < 32; r += 8)
        tile[ty + r][tx] = src[(size_t)(k0 + ty + r) * N + n0 + tx];
    __syncthreads();
    const size_t obase = ((size_t)a * N + n0) * K + k0;
#pragma unroll
    for (int r = 0; r < 32; r += 8) {
        float v = tile[tx][ty + r];
        __half h = __float2half_rn(v);
        dhi[obase + (size_t)(ty + r) * K + tx] = h;
        dlo[obase + (size_t)(ty + r) * K + tx] = __float2half_rn(v - __half2float(h));
    }
}

// ======================================================================
// Batched GEMM: O = [relu](A @ (Whi+Wlo)^T + bias).
// A: fp16 [M,K]; W planes: [NSLOT][N,K] fp16 hi/lo.
// 2 MMA products per tile: a*bhi + a*blo.
// outmode 0: write fp16 plane. outmode 1: fp32 (main/alt).
// ======================================================================
__global__ void __launch_bounds__(NT, 1)
gemm_mma(const __half* __restrict__ Abase, size_t sAz,
         const __half* __restrict__ Whi, const __half* __restrict__ Wlo, size_t sWz,
         const float* __restrict__ bmain, size_t sbz, const float* __restrict__ balt,
         __half* __restrict__ Oh, size_t sOz,
         float* __restrict__ Ofm, size_t sOfz, int ldo_f,
         float* __restrict__ Ofa, int ldo_a,
         int K, int ldn, int relu_f, int outmode)
{
    extern __shared__ __align__(16) char smem[];
    const uint32_t smem_base = smem_u32(smem);
    const int tid  = threadIdx.x;
    const int wid  = tid >> 5;
    const int lane = tid & 31;
    const int wm   = wid >> 2;
    const int wn   = wid & 3;
    const int a   = blockIdx.z;
    const int m0  = blockIdx.x * BM;
    const int n0  = blockIdx.y * BN;

    const __half* As  = Abase + (size_t)a * sAz;
    const __half* Whs = Whi + (size_t)a * sWz;
    const __half* Wls = Wlo + (size_t)a * sWz;
    const float* bsel = (a < ADIM) ? (bmain + (size_t)a * sbz) : balt;

    float* sBias = (float*)(smem + SM_BIAS);
    if (tid < BN) sBias[tid] = bsel[n0 + tid];

    const size_t Ksz = (size_t)K;

    // cp.async tasks: A 512 16B-chunks -> 2/thread; B 2 planes -> 4/thread.
    auto prefetch = [&](int stage, int c) {
        const uint32_t sb = smem_base + stage * STAGE_BYTES;
        const size_t kA = (size_t)c * BK;
#pragma unroll
        for (int r = 0; r < 2; ++r) {
            int t = tid + r * NT;
            int row = t >> 2, ch = t & 3;
            size_t off = (size_t)(m0 + row) * Ksz + kA + ch * 8;
            cpasync16(sb + SM_A + row * 80 + ch * 16, As + off);
        }
#pragma unroll
        for (int r = 0; r < 2; ++r) {
            int t = tid + r * NT;
            int row = t >> 2, ch = t & 3;
            size_t off = (size_t)(n0 + row) * Ksz + kA + ch * 8;
            uint32_t d = sb + SM_BHI + row * 80 + ch * 16;
            cpasync16(d, Whs + off);
            cpasync16(d + (SM_BLO - SM_BHI), Wls + off);
        }
    };

    float acc[4][4][4];
#pragma unroll
    for (int i = 0; i < 4; ++i)
#pragma unroll
        for (int j = 0; j < 4; ++j)
#pragma unroll
            for (int q = 0; q < 4; ++q) acc[i][j][q] = 0.f;

    const int arow  = wm * 64 + (lane & 15);
    const int acol8 = (lane >> 4) * 8;
    const int brow  = wn * 32 + (lane & 7);
    const int bcol8 = ((lane >> 3) & 1) * 8;

    const int nch = K / BK;     // >= 8
    prefetch(0, 0); CP_COMMIT();
    prefetch(1, 1); CP_COMMIT();
    prefetch(2, 2); CP_COMMIT();

    for (int c = 0; c < nch; ++c) {
        CP_WAIT2();
        __syncthreads();
        if (c + 3 < nch) prefetch((c + 3) & 3, c + 3);
        CP_COMMIT();

        const uint32_t sb = smem_base + (c & 3) * STAGE_BYTES;
        const uint32_t aB = sb + SM_A, bHiB = sb + SM_BHI, bLoB = sb + SM_BLO;

#pragma unroll
        for (int ks = 0; ks < 2; ++ks) {
            uint32_t af[4][4], bh[4][2], bl[4][2];
#pragma unroll
            for (int i = 0; i < 4; ++i) {
                uint32_t off = (uint32_t)((arow + i * 16) * SROW + ks * 16 + acol8) * 2;
                ldm_x4(af[i], aB + off);
            }
#pragma unroll
            for (int j = 0; j < 4; ++j) {
                uint32_t off = (uint32_t)((brow + j * 8) * SROW + ks * 16 + bcol8) * 2;
                ldm_x2(bh[j], bHiB + off);
                ldm_x2(bl[j], bLoB + off);
            }
#pragma unroll
            for (int i = 0; i < 4; ++i)
#pragma unroll
                for (int j = 0; j < 4; ++j) {
                    mma16816(acc[i][j], af[i], bh[j]);
                    mma16816(acc[i][j], af[i], bl[j]);
                }
        }
        __syncthreads();
    }

    // ---- epilogue ----
    const int erow0 = wm * 64 + (lane >> 2);
    const int ecol  = wn * 32 + 2 * (lane & 3);

    if (outmode == 0) {
        __half* OhS = Oh + (size_t)a * sOz;
#pragma unroll
        for (int i = 0; i < 4; ++i) {
#pragma unroll
            for (int j = 0; j < 4; ++j) {
                int n_loc = ecol + j * 8;
                float bx = sBias[n_loc], by = sBias[n_loc + 1];
                float vx0 = acc[i][j][0] + bx, vy0 = acc[i][j][1] + by;
                float vx1 = acc[i][j][2] + bx, vy1 = acc[i][j][3] + by;
                if (relu_f) {
                    vx0 = fmaxf(vx0, 0.f); vy0 = fmaxf(vy0, 0.f);
                    vx1 = fmaxf(vx1, 0.f); vy1 = fmaxf(vy1, 0.f);
                }
                size_t p0 = (size_t)(m0 + erow0 + i * 16) * (size_t)ldn + n0 + n_loc;
                size_t p1 = (size_t)(m0 + erow0 + i * 16 + 8) * (size_t)ldn + n0 + n_loc;
                *reinterpret_cast<__half2*>(OhS + p0) = __floats2half2_rn(vx0, vy0);
                *reinterpret_cast<__half2*>(OhS + p1) = __floats2half2_rn(vx1, vy1);
            }
        }
    } else {
        float* Op;
        int ldo;
        if (a < ADIM) { Op = Ofm + (size_t)a * sOfz; ldo = ldo_f; }
        else          { Op = Ofa;                    ldo = ldo_a; }
#pragma unroll
        for (int i = 0; i < 4; ++i) {
#pragma unroll
            for (int j = 0; j < 4; ++j) {
                int n_loc = ecol + j * 8;
                float bx = sBias[n_loc], by = sBias[n_loc + 1];
                float2 v0, v1;
                v0.x = acc[i][j][0] + bx; v0.y = acc[i][j][1] + by;
                v1.x = acc[i][j][2] + bx; v1.y = acc[i][j][3] + by;
                if (relu_f) {
                    v0.x = fmaxf(v0.x, 0.f); v0.y = fmaxf(v0.y, 0.f);
                    v1.x = fmaxf(v1.x, 0.f); v1.y = fmaxf(v1.y, 0.f);
                }
                float* p0 = Op + (size_t)(m0 + erow0 + i * 16) * (size_t)ldo + n0 + n_loc;
                float* p1 = Op + (size_t)(m0 + erow0 + i * 16 + 8) * (size_t)ldo + n0 + n_loc;
                *reinterpret_cast<float2*>(p0) = v0;
                *reinterpret_cast<float2*>(p1) = v1;
            }
        }
    }
}

// ======================================================================
// Combine: psi[b,a,s] = state[b,s] + adv[b,a,s] - mean_a(adv[b,a,s])
// ======================================================================
__global__ void combine_kernel(float* __restrict__ out, const float* __restrict__ state) {
    int idx = blockIdx.x * blockDim.x + threadIdx.x;
    int b = idx >> 6;
    int s4 = (idx & 63) << 2;
    float4* base = reinterpret_cast<float4*>(out + (size_t)b * (ADIM * SF) + s4);
    float4 adv[ADIM];
    float sx = 0.f, sy = 0.f, sz = 0.f, sw = 0.f;
#pragma unroll
    for (int a2 = 0; a2 < ADIM; ++a2) {
        adv[a2] = base[a2 * (SF / 4)];
        sx += adv[a2].x; sy += adv[a2].y; sz += adv[a2].z; sw += adv[a2].w;
    }
    const float inv = 1.0f / ADIM;
    float4 st = *reinterpret_cast<const float4*>(state + (size_t)b * SF + s4);
    float mx = st.x - sx * inv, my = st.y - sy * inv;
    float mz = st.z - sz * inv, mw = st.w - sw * inv;
#pragma unroll
    for (int a2 = 0; a2 < ADIM; ++a2) {
        float4 v;
        v.x = adv[a2].x + mx; v.y = adv[a2].y + my;
        v.z = adv[a2].z + mz; v.w = adv[a2].w + mw;
        base[a2 * (SF / 4)] = v;
    }
}

// ======================================================================
extern "C" void kernel_launch(void* const* d_in, const int* in_sizes, int n_in,
                              void* d_out, int out_size) {
    const float* x  = (const float*)d_in[0];
    const float* W1 = (const float*)d_in[1];
    const float* b1 = (const float*)d_in[2];
    const float* W2 = (const float*)d_in[3];
    const float* b2 = (const float*)d_in[4];
    const float* W3 = (const float*)d_in[5];
    const float* b3 = (const float*)d_in[6];
    const float* V1 = (const float*)d_in[7];
    const float* c1 = (const float*)d_in[8];
    const float* V2 = (const float*)d_in[9];
    const float* c2 = (const float*)d_in[10];
    const float* V3 = (const float*)d_in[11];
    const float* c3 = (const float*)d_in[12];
    float* out = (float*)d_out;

    __half *xh, *H1, *H2;
    __half *W1hi, *W1lo, *W2hi, *W2lo, *W3hi, *W3lo;
    float* S;
    cudaGetSymbolAddress((void**)&xh,   g_x);
    cudaGetSymbolAddress((void**)&H1,   g_H1);
    cudaGetSymbolAddress((void**)&H2,   g_H2);
    cudaGetSymbolAddress((void**)&W1hi, g_W1hi);
    cudaGetSymbolAddress((void**)&W1lo, g_W1lo);
    cudaGetSymbolAddress((void**)&W2hi, g_W2hi);
    cudaGetSymbolAddress((void**)&W2lo, g_W2lo);
    cudaGetSymbolAddress((void**)&W3hi, g_W3hi);
    cudaGetSymbolAddress((void**)&W3lo, g_W3lo);
    cudaGetSymbolAddress((void**)&S,    g_S);

    cudaFuncSetAttribute(gemm_mma, cudaFuncAttributeMaxDynamicSharedMemorySize, SMEM_TOTAL);

    // ---- prologue: round x to fp16; transpose+split weights exactly ----
    round_kernel<<<(B_DIM * SF / 4 + 255) / 256, 256>>>(x, xh, B_DIM * SF / 4);
    transpose_split<<<dim3(SF / 32, FC / 32, NSLOT), dim3(32, 8)>>>(
        W1, (size_t)SF * FC, V1, W1hi, W1lo, SF, FC);
    transpose_split<<<dim3(FC / 32, FC / 32, NSLOT), dim3(32, 8)>>>(
        W2, (size_t)FC * FC, V2, W2hi, W2lo, FC, FC);
    transpose_split<<<dim3(FC / 32, SF / 32, NSLOT), dim3(32, 8)>>>(
        W3, (size_t)FC * SF, V3, W3hi, W3lo, FC, SF);

    const size_t sH = (size_t)B_DIM * FC;

    // Layer 1: x[B,256] @ W1^T -> H1 fp16 (A stride 0: all slots read x)
    gemm_mma<<<dim3(B_DIM / BM, FC / BN, NSLOT), NT, SMEM_TOTAL>>>(
        xh, 0,
        W1hi, W1lo, (size_t)FC * SF,
        b1, FC, c1,
        H1, sH,
        nullptr, 0, 0, nullptr, 0,
        SF, FC, 1, 0);

    // Layer 2: H1 @ W2^T -> H2 fp16
    gemm_mma<<<dim3(B_DIM / BM, FC / BN, NSLOT), NT, SMEM_TOTAL>>>(
        H1, sH,
        W2hi, W2lo, (size_t)FC * FC,
        b2, FC, c2,
        H2, sH,
        nullptr, 0, 0, nullptr, 0,
        FC, FC, 1, 0);

    // Layer 3: H2 @ W3^T -> adv (fp32, into out) ; slot 16 -> g_S
    gemm_mma<<<dim3(B_DIM / BM, SF / BN, NSLOT), NT, SMEM_TOTAL>>>(
        H2, sH,
        W3hi, W3lo, (size_t)SF * FC,
        b3, SF, c3,
        nullptr, 0,
        out, SF, ADIM * SF,
        S, SF,
        FC, SF, 0, 1);

    // Combine
    combine_kernel<<<(B_DIM * SF / 4) / 256, 256>>>(out, S);
}

// round 9
// speedup vs baseline: 2.2982x; 1.5083x over previous
#include <cuda_runtime.h>
#include <cuda_fp16.h>
#include <cstdint>

// ---------------- problem dims ----------------
#define B_DIM 4096
#define SF    256
#define FC    512
#define ADIM  16
#define NSLOT 17            // 16 advantage slots + 1 state slot

// ---------------- GEMM tiles ------------------
#define BM 128
#define BN 128
#define BK 32
#define NT 256              // 8 warps: 2 (M) x 4 (N), warp tile 64x32

#define SROW   40                        // smem row stride in halves = 80 bytes
#define PLANE  (128 * SROW * 2)          // 10240 B per plane (128 rows)
#define SM_A   0
#define SM_B   PLANE
#define STAGE_BYTES (2 * PLANE)          // 20480
#define STAGES 4
#define SM_BIAS (STAGES * STAGE_BYTES)   // 81920
#define SMEM_TOTAL (SM_BIAS + BN * 4)    // 82432

// ---------------- device scratch (no cudaMalloc allowed) ----
__device__ __half g_x[(size_t)B_DIM * SF];                    // fp16 activations
__device__ __half g_H1[(size_t)NSLOT * B_DIM * FC];
__device__ __half g_H2[(size_t)NSLOT * B_DIM * FC];
// transposed fp16 weights: [slot][N][K]
__device__ __half g_W1[(size_t)NSLOT * FC * SF];
__device__ __half g_W2[(size_t)NSLOT * FC * FC];
__device__ __half g_W3[(size_t)NSLOT * SF * FC];
__device__ float g_S[(size_t)B_DIM * SF];

// ---------------- helpers ----------------
__device__ __forceinline__ uint32_t smem_u32(const void* p) {
    uint32_t a;
    asm("{ .reg .u64 t; cvta.to.shared.u64 t, %1; cvt.u32.u64 %0, t; }" : "=r"(a) : "l"(p));
    return a;
}
__device__ __forceinline__ void ldm_x4(uint32_t* r, uint32_t addr) {
    asm volatile("ldmatrix.sync.aligned.m8n8.x4.shared.b16 {%0,%1,%2,%3}, [%4];"
                 : "=r"(r[0]), "=r"(r[1]), "=r"(r[2]), "=r"(r[3]) : "r"(addr));
}
__device__ __forceinline__ void mma16816(float* d, const uint32_t* a, const uint32_t* b) {
    asm volatile("mma.sync.aligned.m16n8k16.row.col.f32.f16.f16.f32 "
                 "{%0,%1,%2,%3}, {%4,%5,%6,%7}, {%8,%9}, {%0,%1,%2,%3};"
                 : "+f"(d[0]), "+f"(d[1]), "+f"(d[2]), "+f"(d[3])
                 : "r"(a[0]), "r"(a[1]), "r"(a[2]), "r"(a[3]), "r"(b[0]), "r"(b[1]));
}
__device__ __forceinline__ void cpasync16(uint32_t dst, const void* src) {
    asm volatile("cp.async.cg.shared.global [%0], [%1], 16;" :: "r"(dst), "l"(src));
}
#define CP_COMMIT() asm volatile("cp.async.commit_group;" ::: "memory")
#define CP_WAIT2()  asm volatile("cp.async.wait_group 2;" ::: "memory")

// ======================================================================
// Prologue 1: round fp32 -> fp16 (activations input)
// ======================================================================
__global__ void round_kernel(const float* __restrict__ src,
                             __half* __restrict__ dst, int n4) {
    int i = blockIdx.x * blockDim.x + threadIdx.x;
    if (i >= n4) return;
    float4 v = reinterpret_cast<const float4*>(src)[i];
    __half2 h0 = __floats2half2_rn(v.x, v.y);
    __half2 h1 = __floats2half2_rn(v.z, v.w);
    reinterpret_cast<__half2*>(dst)[2 * i] = h0;
    reinterpret_cast<__half2*>(dst)[2 * i + 1] = h1;
}

// ======================================================================
// Prologue 2: transpose [K,N] fp32 -> [N,K] fp16; slot 16 = alt src
// ======================================================================
__global__ void transpose_round(const float* __restrict__ src_main, size_t sstride,
                                const float* __restrict__ src_alt,
                                __half* __restrict__ dst, int K, int N) {
    __shared__ float tile[32][33];
    const int a = blockIdx.z;
    const float* src = (a < ADIM) ? (src_main + (size_t)a * sstride) : src_alt;
    const int k0 = blockIdx.x * 32, n0 = blockIdx.y * 32;
    const int tx = threadIdx.x, ty = threadIdx.y;   // 32 x 8
#pragma unroll
    for (int r = 0; r < 32; r += 8)
        tile[ty + r][tx] = src[(size_t)(k0 + ty + r) * N + n0 + tx];
    __syncthreads();
    const size_t obase = ((size_t)a * N + n0) * K + k0;
#pragma unroll
    for (int r = 0; r < 32; r += 8)
        dst[obase + (size_t)(ty + r) * K + tx] = __float2half_rn(tile[tx][ty + r]);
}

// ======================================================================
// Batched GEMM: O = [relu](A @ W^T + bias), pure fp16 operands, fp32 accum.
// A: fp16 [M,K]; W: [NSLOT][N,K] fp16.
// outmode 0: write fp16 plane. outmode 1: fp32 (main/alt).
// ======================================================================
__global__ void __launch_bounds__(NT, 1)
gemm_mma(const __half* __restrict__ Abase, size_t sAz,
         const __half* __restrict__ Wbase, size_t sWz,
         const float* __restrict__ bmain, size_t sbz, const float* __restrict__ balt,
         __half* __restrict__ Oh, size_t sOz,
         float* __restrict__ Ofm, size_t sOfz, int ldo_f,
         float* __restrict__ Ofa, int ldo_a,
         int K, int ldn, int relu_f, int outmode)
{
    extern __shared__ __align__(16) char smem[];
    const uint32_t smem_base = smem_u32(smem);
    const int tid  = threadIdx.x;
    const int wid  = tid >> 5;
    const int lane = tid & 31;
    const int wm   = wid >> 2;
    const int wn   = wid & 3;
    const int a   = blockIdx.z;
    const int m0  = blockIdx.x * BM;
    const int n0  = blockIdx.y * BN;

    const __half* As = Abase + (size_t)a * sAz;
    const __half* Ws = Wbase + (size_t)a * sWz;
    const float* bsel = (a < ADIM) ? (bmain + (size_t)a * sbz) : balt;

    float* sBias = (float*)(smem + SM_BIAS);
    if (tid < BN) sBias[tid] = bsel[n0 + tid];

    const size_t Ksz = (size_t)K;

    // cp.async tasks: 512 16B-chunks per plane -> 2/thread each for A and B.
    auto prefetch = [&](int stage, int c) {
        const uint32_t sb = smem_base + stage * STAGE_BYTES;
        const size_t kA = (size_t)c * BK;
#pragma unroll
        for (int r = 0; r < 2; ++r) {
            int t = tid + r * NT;
            int row = t >> 2, ch = t & 3;
            size_t offA = (size_t)(m0 + row) * Ksz + kA + ch * 8;
            cpasync16(sb + SM_A + row * 80 + ch * 16, As + offA);
            size_t offB = (size_t)(n0 + row) * Ksz + kA + ch * 8;
            cpasync16(sb + SM_B + row * 80 + ch * 16, Ws + offB);
        }
    };

    float acc[4][4][4];
#pragma unroll
    for (int i = 0; i < 4; ++i)
#pragma unroll
        for (int j = 0; j < 4; ++j)
#pragma unroll
            for (int q = 0; q < 4; ++q) acc[i][j][q] = 0.f;

    // A x4 fragment addressing (validated R2..R8)
    const int arow  = wm * 64 + (lane & 15);
    const int acol8 = (lane >> 4) * 8;
    // B x4 addressing (validated R5): one x4 covers 16 N-rows (two j frags)
    const int brow_l = (lane >> 4) * 8 + (lane & 7);
    const int bk_l   = ((lane >> 3) & 1) * 8;

    const int nch = K / BK;     // >= 8
    prefetch(0, 0); CP_COMMIT();
    prefetch(1, 1); CP_COMMIT();
    prefetch(2, 2); CP_COMMIT();

    for (int c = 0; c < nch; ++c) {
        CP_WAIT2();
        __syncthreads();
        if (c + 3 < nch) prefetch((c + 3) & 3, c + 3);
        CP_COMMIT();

        const uint32_t sb = smem_base + (c & 3) * STAGE_BYTES;
        const uint32_t aB = sb + SM_A, bB = sb + SM_B;

#pragma unroll
        for (int ks = 0; ks < 2; ++ks) {
            uint32_t af[4][4], bf[4][2];
#pragma unroll
            for (int i = 0; i < 4; ++i) {
                uint32_t off = (uint32_t)((arow + i * 16) * SROW + ks * 16 + acol8) * 2;
                ldm_x4(af[i], aB + off);
            }
#pragma unroll
            for (int p = 0; p < 2; ++p) {
                uint32_t off = (uint32_t)((wn * 32 + p * 16 + brow_l) * SROW + ks * 16 + bk_l) * 2;
                ldm_x4(&bf[2 * p][0], bB + off);
            }
#pragma unroll
            for (int i = 0; i < 4; ++i)
#pragma unroll
                for (int j = 0; j < 4; ++j)
                    mma16816(acc[i][j], af[i], bf[j]);
        }
        __syncthreads();
    }

    // ---- epilogue ----
    const int erow0 = wm * 64 + (lane >> 2);
    const int ecol  = wn * 32 + 2 * (lane & 3);

    if (outmode == 0) {
        __half* OhS = Oh + (size_t)a * sOz;
#pragma unroll
        for (int i = 0; i < 4; ++i) {
#pragma unroll
            for (int j = 0; j < 4; ++j) {
                int n_loc = ecol + j * 8;
                float bx = sBias[n_loc], by = sBias[n_loc + 1];
                float vx0 = acc[i][j][0] + bx, vy0 = acc[i][j][1] + by;
                float vx1 = acc[i][j][2] + bx, vy1 = acc[i][j][3] + by;
                if (relu_f) {
                    vx0 = fmaxf(vx0, 0.f); vy0 = fmaxf(vy0, 0.f);
                    vx1 = fmaxf(vx1, 0.f); vy1 = fmaxf(vy1, 0.f);
                }
                size_t p0 = (size_t)(m0 + erow0 + i * 16) * (size_t)ldn + n0 + n_loc;
                size_t p1 = (size_t)(m0 + erow0 + i * 16 + 8) * (size_t)ldn + n0 + n_loc;
                *reinterpret_cast<__half2*>(OhS + p0) = __floats2half2_rn(vx0, vy0);
                *reinterpret_cast<__half2*>(OhS + p1) = __floats2half2_rn(vx1, vy1);
            }
        }
    } else {
        float* Op;
        int ldo;
        if (a < ADIM) { Op = Ofm + (size_t)a * sOfz; ldo = ldo_f; }
        else          { Op = Ofa;                    ldo = ldo_a; }
#pragma unroll
        for (int i = 0; i < 4; ++i) {
#pragma unroll
            for (int j = 0; j < 4; ++j) {
                int n_loc = ecol + j * 8;
                float bx = sBias[n_loc], by = sBias[n_loc + 1];
                float2 v0, v1;
                v0.x = acc[i][j][0] + bx; v0.y = acc[i][j][1] + by;
                v1.x = acc[i][j][2] + bx; v1.y = acc[i][j][3] + by;
                if (relu_f) {
                    v0.x = fmaxf(v0.x, 0.f); v0.y = fmaxf(v0.y, 0.f);
                    v1.x = fmaxf(v1.x, 0.f); v1.y = fmaxf(v1.y, 0.f);
                }
                float* p0 = Op + (size_t)(m0 + erow0 + i * 16) * (size_t)ldo + n0 + n_loc;
                float* p1 = Op + (size_t)(m0 + erow0 + i * 16 + 8) * (size_t)ldo + n0 + n_loc;
                *reinterpret_cast<float2*>(p0) = v0;
                *reinterpret_cast<float2*>(p1) = v1;
            }
        }
    }
}

// ======================================================================
// Combine: psi[b,a,s] = state[b,s] + adv[b,a,s] - mean_a(adv[b,a,s])
// ======================================================================
__global__ void combine_kernel(float* __restrict__ out, const float* __restrict__ state) {
    int idx = blockIdx.x * blockDim.x + threadIdx.x;
    int b = idx >> 6;
    int s4 = (idx & 63) << 2;
    float4* base = reinterpret_cast<float4*>(out + (size_t)b * (ADIM * SF) + s4);
    float4 adv[ADIM];
    float sx = 0.f, sy = 0.f, sz = 0.f, sw = 0.f;
#pragma unroll
    for (int a2 = 0; a2 < ADIM; ++a2) {
        adv[a2] = base[a2 * (SF / 4)];
        sx += adv[a2].x; sy += adv[a2].y; sz += adv[a2].z; sw += adv[a2].w;
    }
    const float inv = 1.0f / ADIM;
    float4 st = *reinterpret_cast<const float4*>(state + (size_t)b * SF + s4);
    float mx = st.x - sx * inv, my = st.y - sy * inv;
    float mz = st.z - sz * inv, mw = st.w - sw * inv;
#pragma unroll
    for (int a2 = 0; a2 < ADIM; ++a2) {
        float4 v;
        v.x = adv[a2].x + mx; v.y = adv[a2].y + my;
        v.z = adv[a2].z + mz; v.w = adv[a2].w + mw;
        base[a2 * (SF / 4)] = v;
    }
}

// ======================================================================
extern "C" void kernel_launch(void* const* d_in, const int* in_sizes, int n_in,
                              void* d_out, int out_size) {
    const float* x  = (const float*)d_in[0];
    const float* W1 = (const float*)d_in[1];
    const float* b1 = (const float*)d_in[2];
    const float* W2 = (const float*)d_in[3];
    const float* b2 = (const float*)d_in[4];
    const float* W3 = (const float*)d_in[5];
    const float* b3 = (const float*)d_in[6];
    const float* V1 = (const float*)d_in[7];
    const float* c1 = (const float*)d_in[8];
    const float* V2 = (const float*)d_in[9];
    const float* c2 = (const float*)d_in[10];
    const float* V3 = (const float*)d_in[11];
    const float* c3 = (const float*)d_in[12];
    float* out = (float*)d_out;

    __half *xh, *H1, *H2, *W1t, *W2t, *W3t;
    float* S;
    cudaGetSymbolAddress((void**)&xh,  g_x);
    cudaGetSymbolAddress((void**)&H1,  g_H1);
    cudaGetSymbolAddress((void**)&H2,  g_H2);
    cudaGetSymbolAddress((void**)&W1t, g_W1);
    cudaGetSymbolAddress((void**)&W2t, g_W2);
    cudaGetSymbolAddress((void**)&W3t, g_W3);
    cudaGetSymbolAddress((void**)&S,   g_S);

    cudaFuncSetAttribute(gemm_mma, cudaFuncAttributeMaxDynamicSharedMemorySize, SMEM_TOTAL);

    // ---- prologue: round x to fp16; transpose+round weights ----
    round_kernel<<<(B_DIM * SF / 4 + 255) / 256, 256>>>(x, xh, B_DIM * SF / 4);
    transpose_round<<<dim3(SF / 32, FC / 32, NSLOT), dim3(32, 8)>>>(
        W1, (size_t)SF * FC, V1, W1t, SF, FC);
    transpose_round<<<dim3(FC / 32, FC / 32, NSLOT), dim3(32, 8)>>>(
        W2, (size_t)FC * FC, V2, W2t, FC, FC);
    transpose_round<<<dim3(FC / 32, SF / 32, NSLOT), dim3(32, 8)>>>(
        W3, (size_t)FC * SF, V3, W3t, FC, SF);

    const size_t sH = (size_t)B_DIM * FC;

    // Layer 1: x[B,256] @ W1^T -> H1 fp16 (A stride 0: all slots read x)
    gemm_mma<<<dim3(B_DIM / BM, FC / BN, NSLOT), NT, SMEM_TOTAL>>>(
        xh, 0,
        W1t, (size_t)FC * SF,
        b1, FC, c1,
        H1, sH,
        nullptr, 0, 0, nullptr, 0,
        SF, FC, 1, 0);

    // Layer 2: H1 @ W2^T -> H2 fp16
    gemm_mma<<<dim3(B_DIM / BM, FC / BN, NSLOT), NT, SMEM_TOTAL>>>(
        H1, sH,
        W2t, (size_t)FC * FC,
        b2, FC, c2,
        H2, sH,
        nullptr, 0, 0, nullptr, 0,
        FC, FC, 1, 0);

    // Layer 3: H2 @ W3^T -> adv (fp32, into out) ; slot 16 -> g_S
    gemm_mma<<<dim3(B_DIM / BM, SF / BN, NSLOT), NT, SMEM_TOTAL>>>(
        H2, sH,
        W3t, (size_t)SF * FC,
        b3, SF, c3,
        nullptr, 0,
        out, SF, ADIM * SF,
        S, SF,
        FC, SF, 0, 1);

    // Combine
    combine_kernel<<<(B_DIM * SF / 4) / 256, 256>>>(out, S);
}

// round 10
// speedup vs baseline: 2.2989x; 1.0003x over previous
#include <cuda_runtime.h>
#include <cuda_fp16.h>
#include <cstdint>

// ---------------- problem dims ----------------
#define B_DIM 4096
#define SF    256
#define FC    512
#define ADIM  16
#define NSLOT 17            // 16 advantage slots + 1 state slot

// ---------------- GEMM tiles ------------------
#define BM 128
#define BN 128
#define BK 32
#define NT 256              // 8 warps: 2 (M) x 4 (N), warp tile 64x32

#define SROW   40                        // smem row stride in halves = 80 bytes
#define PLANE  (128 * SROW * 2)          // 10240 B per plane (128 rows)
#define SM_A   0
#define SM_B   PLANE
#define STAGE_BYTES (2 * PLANE)          // 20480
#define STAGES 4
#define SM_BIAS (STAGES * STAGE_BYTES)   // 81920
#define SMEM_TOTAL (SM_BIAS + BN * 4)    // 82432

// ---------------- device scratch (no cudaMalloc allowed) ----
__device__ __half g_x[(size_t)B_DIM * SF];                    // fp16 activations
__device__ __half g_H1[(size_t)NSLOT * B_DIM * FC];
__device__ __half g_H2[(size_t)NSLOT * B_DIM * FC];
// transposed fp16 weights: [slot][N][K]
__device__ __half g_W1[(size_t)NSLOT * FC * SF];
__device__ __half g_W2[(size_t)NSLOT * FC * FC];
__device__ __half g_W3[(size_t)NSLOT * SF * FC];
__device__ float g_S[(size_t)B_DIM * SF];

// ---------------- helpers ----------------
__device__ __forceinline__ uint32_t smem_u32(const void* p) {
    uint32_t a;
    asm("{ .reg .u64 t; cvta.to.shared.u64 t, %1; cvt.u32.u64 %0, t; }" : "=r"(a) : "l"(p));
    return a;
}
__device__ __forceinline__ void ldm_x4(uint32_t* r, uint32_t addr) {
    asm volatile("ldmatrix.sync.aligned.m8n8.x4.shared.b16 {%0,%1,%2,%3}, [%4];"
                 : "=r"(r[0]), "=r"(r[1]), "=r"(r[2]), "=r"(r[3]) : "r"(addr));
}
__device__ __forceinline__ void mma16816(float* d, const uint32_t* a, const uint32_t* b) {
    asm volatile("mma.sync.aligned.m16n8k16.row.col.f32.f16.f16.f32 "
                 "{%0,%1,%2,%3}, {%4,%5,%6,%7}, {%8,%9}, {%0,%1,%2,%3};"
                 : "+f"(d[0]), "+f"(d[1]), "+f"(d[2]), "+f"(d[3])
                 : "r"(a[0]), "r"(a[1]), "r"(a[2]), "r"(a[3]), "r"(b[0]), "r"(b[1]));
}
__device__ __forceinline__ void cpasync16(uint32_t dst, const void* src) {
    asm volatile("cp.async.cg.shared.global [%0], [%1], 16;" :: "r"(dst), "l"(src));
}
#define CP_COMMIT() asm volatile("cp.async.commit_group;" ::: "memory")
#define CP_WAIT2()  asm volatile("cp.async.wait_group 2;" ::: "memory")

// ======================================================================
// Prologue 1: round fp32 -> fp16 (activations input)
// ======================================================================
__global__ void round_kernel(const float* __restrict__ src,
                             __half* __restrict__ dst, int n4) {
    int i = blockIdx.x * blockDim.x + threadIdx.x;
    if (i >= n4) return;
    float4 v = reinterpret_cast<const float4*>(src)[i];
    __half2 h0 = __floats2half2_rn(v.x, v.y);
    __half2 h1 = __floats2half2_rn(v.z, v.w);
    reinterpret_cast<__half2*>(dst)[2 * i] = h0;
    reinterpret_cast<__half2*>(dst)[2 * i + 1] = h1;
}

// ======================================================================
// Prologue 2: transpose [K,N] fp32 -> [N,K] fp16; slot 16 = alt src
// ======================================================================
__global__ void transpose_round(const float* __restrict__ src_main, size_t sstride,
                                const float* __restrict__ src_alt,
                                __half* __restrict__ dst, int K, int N) {
    __shared__ float tile[32][33];
    const int a = blockIdx.z;
    const float* src = (a < ADIM) ? (src_main + (size_t)a * sstride) : src_alt;
    const int k0 = blockIdx.x * 32, n0 = blockIdx.y * 32;
    const int tx = threadIdx.x, ty = threadIdx.y;   // 32 x 8
#pragma unroll
    for (int r = 0; r < 32; r += 8)
        tile[ty + r][tx] = src[(size_t)(k0 + ty + r) * N + n0 + tx];
    __syncthreads();
    const size_t obase = ((size_t)a * N + n0) * K + k0;
#pragma unroll
    for (int r = 0; r < 32; r += 8)
        dst[obase + (size_t)(ty + r) * K + tx] = __float2half_rn(tile[tx][ty + r]);
}

// ======================================================================
// Batched GEMM: O = [relu](A @ W^T + bias), pure fp16 operands, fp32 accum.
// A: fp16 [M,K]; W: [NSLOT][N,K] fp16.
// outmode 0: write fp16 plane. outmode 1: fp32 (main/alt).
// ======================================================================
__global__ void __launch_bounds__(NT, 1)
gemm_mma(const __half* __restrict__ Abase, size_t sAz,
         const __half* __restrict__ Wbase, size_t sWz,
         const float* __restrict__ bmain, size_t sbz, const float* __restrict__ balt,
         __half* __restrict__ Oh, size_t sOz,
         float* __restrict__ Ofm, size_t sOfz, int ldo_f,
         float* __restrict__ Ofa, int ldo_a,
         int K, int ldn, int relu_f, int outmode)
{
    extern __shared__ __align__(16) char smem[];
    const uint32_t smem_base = smem_u32(smem);
    const int tid  = threadIdx.x;
    const int wid  = tid >> 5;
    const int lane = tid & 31;
    const int wm   = wid >> 2;
    const int wn   = wid & 3;
    const int a   = blockIdx.z;
    const int m0  = blockIdx.x * BM;
    const int n0  = blockIdx.y * BN;

    const __half* As = Abase + (size_t)a * sAz;
    const __half* Ws = Wbase + (size_t)a * sWz;
    const float* bsel = (a < ADIM) ? (bmain + (size_t)a * sbz) : balt;

    float* sBias = (float*)(smem + SM_BIAS);
    if (tid < BN) sBias[tid] = bsel[n0 + tid];

    const size_t Ksz = (size_t)K;

    // cp.async tasks: 512 16B-chunks per plane -> 2/thread each for A and B.
    auto prefetch = [&](int stage, int c) {
        const uint32_t sb = smem_base + stage * STAGE_BYTES;
        const size_t kA = (size_t)c * BK;
#pragma unroll
        for (int r = 0; r < 2; ++r) {
            int t = tid + r * NT;
            int row = t >> 2, ch = t & 3;
            size_t offA = (size_t)(m0 + row) * Ksz + kA + ch * 8;
            cpasync16(sb + SM_A + row * 80 + ch * 16, As + offA);
            size_t offB = (size_t)(n0 + row) * Ksz + kA + ch * 8;
            cpasync16(sb + SM_B + row * 80 + ch * 16, Ws + offB);
        }
    };

    float acc[4][4][4];
#pragma unroll
    for (int i = 0; i < 4; ++i)
#pragma unroll
        for (int j = 0; j < 4; ++j)
#pragma unroll
            for (int q = 0; q < 4; ++q) acc[i][j][q] = 0.f;

    // A x4 fragment addressing (validated R2..R8)
    const int arow  = wm * 64 + (lane & 15);
    const int acol8 = (lane >> 4) * 8;
    // B x4 addressing (validated R5): one x4 covers 16 N-rows (two j frags)
    const int brow_l = (lane >> 4) * 8 + (lane & 7);
    const int bk_l   = ((lane >> 3) & 1) * 8;

    const int nch = K / BK;     // >= 8
    prefetch(0, 0); CP_COMMIT();
    prefetch(1, 1); CP_COMMIT();
    prefetch(2, 2); CP_COMMIT();

    for (int c = 0; c < nch; ++c) {
        CP_WAIT2();
        __syncthreads();
        if (c + 3 < nch) prefetch((c + 3) & 3, c + 3);
        CP_COMMIT();

        const uint32_t sb = smem_base + (c & 3) * STAGE_BYTES;
        const uint32_t aB = sb + SM_A, bB = sb + SM_B;

#pragma unroll
        for (int ks = 0; ks < 2; ++ks) {
            uint32_t af[4][4], bf[4][2];
#pragma unroll
            for (int i = 0; i < 4; ++i) {
                uint32_t off = (uint32_t)((arow + i * 16) * SROW + ks * 16 + acol8) * 2;
                ldm_x4(af[i], aB + off);
            }
#pragma unroll
            for (int p = 0; p < 2; ++p) {
                uint32_t off = (uint32_t)((wn * 32 + p * 16 + brow_l) * SROW + ks * 16 + bk_l) * 2;
                ldm_x4(&bf[2 * p][0], bB + off);
            }
#pragma unroll
            for (int i = 0; i < 4; ++i)
#pragma unroll
                for (int j = 0; j < 4; ++j)
                    mma16816(acc[i][j], af[i], bf[j]);
        }
        __syncthreads();
    }

    // ---- epilogue ----
    const int erow0 = wm * 64 + (lane >> 2);
    const int ecol  = wn * 32 + 2 * (lane & 3);

    if (outmode == 0) {
        __half* OhS = Oh + (size_t)a * sOz;
#pragma unroll
        for (int i = 0; i < 4; ++i) {
#pragma unroll
            for (int j = 0; j < 4; ++j) {
                int n_loc = ecol + j * 8;
                float bx = sBias[n_loc], by = sBias[n_loc + 1];
                float vx0 = acc[i][j][0] + bx, vy0 = acc[i][j][1] + by;
                float vx1 = acc[i][j][2] + bx, vy1 = acc[i][j][3] + by;
                if (relu_f) {
                    vx0 = fmaxf(vx0, 0.f); vy0 = fmaxf(vy0, 0.f);
                    vx1 = fmaxf(vx1, 0.f); vy1 = fmaxf(vy1, 0.f);
                }
                size_t p0 = (size_t)(m0 + erow0 + i * 16) * (size_t)ldn + n0 + n_loc;
                size_t p1 = (size_t)(m0 + erow0 + i * 16 + 8) * (size_t)ldn + n0 + n_loc;
                *reinterpret_cast<__half2*>(OhS + p0) = __floats2half2_rn(vx0, vy0);
                *reinterpret_cast<__half2*>(OhS + p1) = __floats2half2_rn(vx1, vy1);
            }
        }
    } else {
        float* Op;
        int ldo;
        if (a < ADIM) { Op = Ofm + (size_t)a * sOfz; ldo = ldo_f; }
        else          { Op = Ofa;                    ldo = ldo_a; }
#pragma unroll
        for (int i = 0; i < 4; ++i) {
#pragma unroll
            for (int j = 0; j < 4; ++j) {
                int n_loc = ecol + j * 8;
                float bx = sBias[n_loc], by = sBias[n_loc + 1];
                float2 v0, v1;
                v0.x = acc[i][j][0] + bx; v0.y = acc[i][j][1] + by;
                v1.x = acc[i][j][2] + bx; v1.y = acc[i][j][3] + by;
                if (relu_f) {
                    v0.x = fmaxf(v0.x, 0.f); v0.y = fmaxf(v0.y, 0.f);
                    v1.x = fmaxf(v1.x, 0.f); v1.y = fmaxf(v1.y, 0.f);
                }
                float* p0 = Op + (size_t)(m0 + erow0 + i * 16) * (size_t)ldo + n0 + n_loc;
                float* p1 = Op + (size_t)(m0 + erow0 + i * 16 + 8) * (size_t)ldo + n0 + n_loc;
                *reinterpret_cast<float2*>(p0) = v0;
                *reinterpret_cast<float2*>(p1) = v1;
            }
        }
    }
}

// ======================================================================
// Combine: psi[b,a,s] = state[b,s] + adv[b,a,s] - mean_a(adv[b,a,s])
// ======================================================================
__global__ void combine_kernel(float* __restrict__ out, const float* __restrict__ state) {
    int idx = blockIdx.x * blockDim.x + threadIdx.x;
    int b = idx >> 6;
    int s4 = (idx & 63) << 2;
    float4* base = reinterpret_cast<float4*>(out + (size_t)b * (ADIM * SF) + s4);
    float4 adv[ADIM];
    float sx = 0.f, sy = 0.f, sz = 0.f, sw = 0.f;
#pragma unroll
    for (int a2 = 0; a2 < ADIM; ++a2) {
        adv[a2] = base[a2 * (SF / 4)];
        sx += adv[a2].x; sy += adv[a2].y; sz += adv[a2].z; sw += adv[a2].w;
    }
    const float inv = 1.0f / ADIM;
    float4 st = *reinterpret_cast<const float4*>(state + (size_t)b * SF + s4);
    float mx = st.x - sx * inv, my = st.y - sy * inv;
    float mz = st.z - sz * inv, mw = st.w - sw * inv;
#pragma unroll
    for (int a2 = 0; a2 < ADIM; ++a2) {
        float4 v;
        v.x = adv[a2].x + mx; v.y = adv[a2].y + my;
        v.z = adv[a2].z + mz; v.w = adv[a2].w + mw;
        base[a2 * (SF / 4)] = v;
    }
}

// ======================================================================
extern "C" void kernel_launch(void* const* d_in, const int* in_sizes, int n_in,
                              void* d_out, int out_size) {
    const float* x  = (const float*)d_in[0];
    const float* W1 = (const float*)d_in[1];
    const float* b1 = (const float*)d_in[2];
    const float* W2 = (const float*)d_in[3];
    const float* b2 = (const float*)d_in[4];
    const float* W3 = (const float*)d_in[5];
    const float* b3 = (const float*)d_in[6];
    const float* V1 = (const float*)d_in[7];
    const float* c1 = (const float*)d_in[8];
    const float* V2 = (const float*)d_in[9];
    const float* c2 = (const float*)d_in[10];
    const float* V3 = (const float*)d_in[11];
    const float* c3 = (const float*)d_in[12];
    float* out = (float*)d_out;

    __half *xh, *H1, *H2, *W1t, *W2t, *W3t;
    float* S;
    cudaGetSymbolAddress((void**)&xh,  g_x);
    cudaGetSymbolAddress((void**)&H1,  g_H1);
    cudaGetSymbolAddress((void**)&H2,  g_H2);
    cudaGetSymbolAddress((void**)&W1t, g_W1);
    cudaGetSymbolAddress((void**)&W2t, g_W2);
    cudaGetSymbolAddress((void**)&W3t, g_W3);
    cudaGetSymbolAddress((void**)&S,   g_S);

    cudaFuncSetAttribute(gemm_mma, cudaFuncAttributeMaxDynamicSharedMemorySize, SMEM_TOTAL);

    // ---- prologue: round x to fp16; transpose+round weights ----
    round_kernel<<<(B_DIM * SF / 4 + 255) / 256, 256>>>(x, xh, B_DIM * SF / 4);
    transpose_round<<<dim3(SF / 32, FC / 32, NSLOT), dim3(32, 8)>>>(
        W1, (size_t)SF * FC, V1, W1t, SF, FC);
    transpose_round<<<dim3(FC / 32, FC / 32, NSLOT), dim3(32, 8)>>>(
        W2, (size_t)FC * FC, V2, W2t, FC, FC);
    transpose_round<<<dim3(FC / 32, SF / 32, NSLOT), dim3(32, 8)>>>(
        W3, (size_t)FC * SF, V3, W3t, FC, SF);

    const size_t sH = (size_t)B_DIM * FC;

    // Layer 1: x[B,256] @ W1^T -> H1 fp16 (A stride 0: all slots read x)
    gemm_mma<<<dim3(B_DIM / BM, FC / BN, NSLOT), NT, SMEM_TOTAL>>>(
        xh, 0,
        W1t, (size_t)FC * SF,
        b1, FC, c1,
        H1, sH,
        nullptr, 0, 0, nullptr, 0,
        SF, FC, 1, 0);

    // Layer 2: H1 @ W2^T -> H2 fp16
    gemm_mma<<<dim3(B_DIM / BM, FC / BN, NSLOT), NT, SMEM_TOTAL>>>(
        H1, sH,
        W2t, (size_t)FC * FC,
        b2, FC, c2,
        H2, sH,
        nullptr, 0, 0, nullptr, 0,
        FC, FC, 1, 0);

    // Layer 3: H2 @ W3^T -> adv (fp32, into out) ; slot 16 -> g_S
    gemm_mma<<<dim3(B_DIM / BM, SF / BN, NSLOT), NT, SMEM_TOTAL>>>(
        H2, sH,
        W3t, (size_t)SF * FC,
        b3, SF, c3,
        nullptr, 0,
        out, SF, ADIM * SF,
        S, SF,
        FC, SF, 0, 1);

    // Combine
    combine_kernel<<<(B_DIM * SF / 4) / 256, 256>>>(out, S);
}